// round 10
// baseline (speedup 1.0000x reference)
#include <cuda_runtime.h>
#include <cuda_fp16.h>
#include <cstdint>

#define SQ 2048
#define DM 1024
#define NH 16
#define MR 4096

static __device__ float g_k[MR*DM];
static __device__ float g_v1s[NH*64];
// fp16 split activations (A side), single-fp16 weights (B side)
static __device__ __half g_qAh[MR*DM], g_qAl[MR*DM];
static __device__ __half g_kAh[MR*DM], g_kAl[MR*DM];
static __device__ __half g_vAh[MR*DM], g_vAl[MR*DM];
static __device__ __half g_wq[DM*DM], g_wk[DM*DM], g_wv[DM*DM], g_wo[DM*DM];
// attention operands
static __device__ __half g_qh[NH*SQ*128], g_ql[NH*SQ*128];
static __device__ __half g_vh[NH*SQ*128], g_vdummy[NH*SQ*128];
static __device__ __half g_kth[NH*128*SQ];
// attention output, split for final GEMM
static __device__ __half g_aoh[MR*DM], g_aol[MR*DM];

// ---------------- PTX helpers ----------------
__device__ __forceinline__ uint32_t s2u(const void* p) {
    uint32_t a;
    asm("{ .reg .u64 t; cvta.to.shared.u64 t, %1; cvt.u32.u64 %0, t; }" : "=r"(a) : "l"(p));
    return a;
}
__device__ __forceinline__ void mma16816(float* d, const uint32_t* a, const uint32_t* b) {
    asm volatile(
        "mma.sync.aligned.m16n8k16.row.col.f32.f16.f16.f32 "
        "{%0,%1,%2,%3}, {%4,%5,%6,%7}, {%8,%9}, {%0,%1,%2,%3};"
        : "+f"(d[0]), "+f"(d[1]), "+f"(d[2]), "+f"(d[3])
        : "r"(a[0]), "r"(a[1]), "r"(a[2]), "r"(a[3]), "r"(b[0]), "r"(b[1]));
}
__device__ __forceinline__ void ldsm4(uint32_t* r, uint32_t addr) {
    asm volatile("ldmatrix.sync.aligned.m8n8.x4.shared.b16 {%0,%1,%2,%3}, [%4];"
        : "=r"(r[0]), "=r"(r[1]), "=r"(r[2]), "=r"(r[3]) : "r"(addr));
}
__device__ __forceinline__ void ldsm4t(uint32_t* r, uint32_t addr) {
    asm volatile("ldmatrix.sync.aligned.m8n8.x4.trans.shared.b16 {%0,%1,%2,%3}, [%4];"
        : "=r"(r[0]), "=r"(r[1]), "=r"(r[2]), "=r"(r[3]) : "r"(addr));
}
__device__ __forceinline__ void cpa16(uint32_t dst, const void* src) {
    asm volatile("cp.async.cg.shared.global [%0], [%1], 16;" :: "r"(dst), "l"(src));
}
__device__ __forceinline__ void cpcommit() {
    asm volatile("cp.async.commit_group;" ::: "memory");
}
__device__ __forceinline__ void cpwait1() {
    asm volatile("cp.async.wait_group 1;" ::: "memory");
}
__device__ __forceinline__ void cpwait0() {
    asm volatile("cp.async.wait_group 0;" ::: "memory");
}
__device__ __forceinline__ uint32_t pack2(__half a, __half b) {
    __half2 t = __halves2half2(a, b);
    return *reinterpret_cast<uint32_t*>(&t);
}
// split fp32x4 -> fp16 hi pair-packed + lo pair-packed
__device__ __forceinline__ void split4(float4 v, uint2& h, uint2& l) {
    __half hx = __float2half_rn(v.x), hy = __float2half_rn(v.y);
    __half hz = __float2half_rn(v.z), hw = __float2half_rn(v.w);
    __half lx = __float2half_rn(v.x - __half2float(hx));
    __half ly = __float2half_rn(v.y - __half2float(hy));
    __half lz = __float2half_rn(v.z - __half2float(hz));
    __half lw = __float2half_rn(v.w - __half2float(hw));
    h.x = pack2(hx, hy); h.y = pack2(hz, hw);
    l.x = pack2(lx, ly); l.y = pack2(lz, lw);
}
// fp32x4 -> fp16 single pair-packed
__device__ __forceinline__ uint2 round4(float4 v) {
    uint2 r;
    r.x = pack2(__float2half_rn(v.x), __float2half_rn(v.y));
    r.y = pack2(__float2half_rn(v.z), __float2half_rn(v.w));
    return r;
}
__device__ __forceinline__ uint32_t packsplit2(float a, float b, uint32_t& lo) {
    __half ah = __float2half_rn(a), bh = __float2half_rn(b);
    __half al = __float2half_rn(a - __half2float(ah));
    __half bl = __float2half_rn(b - __half2float(bh));
    lo = pack2(al, bl);
    return pack2(ah, bh);
}

// ---------------------------------------------------------------------------
// Prep: split fp32 row-major [R][1024] -> fp16 hi/lo (same layout)
// ---------------------------------------------------------------------------
__global__ __launch_bounds__(256) void splitA(const float4* __restrict__ A,
                                              __half* __restrict__ oh,
                                              __half* __restrict__ ol)
{
    size_t i = (size_t)blockIdx.x * 256 + threadIdx.x;
    uint2 h, l; split4(A[i], h, l);
    *(uint2*)&oh[i * 4] = h;
    *(uint2*)&ol[i * 4] = l;
}

// Prep: round fp32 [R][1024] -> single fp16 (Wo path)
__global__ __launch_bounds__(256) void roundA(const float4* __restrict__ A,
                                              __half* __restrict__ o)
{
    size_t i = (size_t)blockIdx.x * 256 + threadIdx.x;
    *(uint2*)&o[i * 4] = round4(A[i]);
}

// Prep: stacked W [16][1024][64] -> single fp16 W'[k][c], W'(k,c)=W[c>>6][k][c&63]
__global__ __launch_bounds__(256) void roundW1(const float* __restrict__ W,
                                               __half* __restrict__ o)
{
    size_t i = (size_t)blockIdx.x * 256 + threadIdx.x;   // over 1024*256 f4s
    int k = (int)(i >> 8);
    int c4 = (int)(i & 255) * 4;
    float4 v = *(const float4*)&W[((size_t)(c4 >> 6) * DM + k) * 64 + (c4 & 63)];
    *(uint2*)&o[(size_t)k * DM + c4] = round4(v);
}

// ---------------------------------------------------------------------------
// fp16 2-term GEMM, cp.async 2-stage pipeline.
// C[4096x1024] = (Ah+Al) @ B + bias,  A [M][1024] hi/lo fp16, B [K][N] fp16.
// EMODE 0: fp32 C.  EMODE 1: split fp16 out in attn layout [h][s][128].
// ---------------------------------------------------------------------------
#define GA_ST 40
#define GB_ST 136
#define SA_SZ (128*GA_ST)     // 5120 elems / stage / array
#define SB_SZ (32*GB_ST)      // 4352
#define OFF_AH(s) ((s)*SA_SZ)
#define OFF_AL(s) (2*SA_SZ + (s)*SA_SZ)
#define OFF_B(s)  (4*SA_SZ + (s)*SB_SZ)
#define GEMM_SMEM ((4*SA_SZ + 2*SB_SZ) * 2)   // 58368 B

template<int EMODE>
__global__ void __launch_bounds__(256, 2) gemm_hf(
    const __half* __restrict__ Ah_g, const __half* __restrict__ Al_g,
    const __half* __restrict__ B_g,
    const float* __restrict__ bias,
    float* __restrict__ C,
    __half* __restrict__ Oh, __half* __restrict__ Ol)
{
    extern __shared__ __half gsm[];
    const uint32_t sb = s2u(gsm);
    const int tid = threadIdx.x;
    const int wid = tid >> 5, lane = tid & 31;
    const int m0 = blockIdx.y * 128, n0 = blockIdx.x * 128;
    const int wm = (wid & 3) * 32;
    const int wn = (wid >> 2) * 64;

    float acc[2][8][4];
#pragma unroll
    for (int i = 0; i < 2; i++)
#pragma unroll
        for (int j = 0; j < 8; j++)
#pragma unroll
            for (int k = 0; k < 4; k++) acc[i][j][k] = 0.f;

    const int aOff = (wm + (lane & 15)) * GA_ST + (lane >> 4) * 8;
    const int bOff = (lane & 15) * GB_ST + wn + (lane >> 4) * 8;

    auto loadStage = [&](int s, int k0) {
#pragma unroll
        for (int t = 0; t < 4; t++) {               // A hi/lo: 1024 chunks
            int c = tid + t * 256;
            int arr = c >> 9, rem = c & 511;
            int m = rem >> 2, j = rem & 3;
            const __half* src = (arr ? Al_g : Ah_g)
                + (size_t)(m0 + m) * DM + k0 + j * 8;
            uint32_t dst = sb + (uint32_t)((arr ? OFF_AL(s) : OFF_AH(s))
                + m * GA_ST + j * 8) * 2;
            cpa16(dst, src);
        }
#pragma unroll
        for (int t = 0; t < 2; t++) {               // B: 512 chunks
            int c = tid + t * 256;
            int k = c >> 4, j = c & 15;
            const __half* src = B_g + (size_t)(k0 + k) * DM + n0 + j * 8;
            uint32_t dst = sb + (uint32_t)(OFF_B(s) + k * GB_ST + j * 8) * 2;
            cpa16(dst, src);
        }
    };

    loadStage(0, 0);
    cpcommit();

    for (int i = 0; i < 32; i++) {
        cpwait0();
        __syncthreads();
        if (i + 1 < 32) {
            loadStage((i + 1) & 1, (i + 1) * 32);
            cpcommit();
        }
        const int s = i & 1;
        const uint32_t ahB = sb + (uint32_t)(OFF_AH(s) + aOff) * 2;
        const uint32_t alB = sb + (uint32_t)(OFF_AL(s) + aOff) * 2;
        const uint32_t bB  = sb + (uint32_t)(OFF_B(s)  + bOff) * 2;
#pragma unroll
        for (int k16 = 0; k16 < 32; k16 += 16) {
            uint32_t ah[2][4], al[2][4];
            ldsm4(ah[0], ahB + (uint32_t)k16 * 2);
            ldsm4(ah[1], ahB + (uint32_t)(16 * GA_ST + k16) * 2);
            ldsm4(al[0], alB + (uint32_t)k16 * 2);
            ldsm4(al[1], alB + (uint32_t)(16 * GA_ST + k16) * 2);
#pragma unroll
            for (int p = 0; p < 4; p++) {
                uint32_t b4[4];
                ldsm4t(b4, bB + (uint32_t)(k16 * GB_ST + p * 16) * 2);
#pragma unroll
                for (int mt = 0; mt < 2; mt++) {
                    mma16816(acc[mt][2 * p],     ah[mt], &b4[0]);
                    mma16816(acc[mt][2 * p + 1], ah[mt], &b4[2]);
                    mma16816(acc[mt][2 * p],     al[mt], &b4[0]);
                    mma16816(acc[mt][2 * p + 1], al[mt], &b4[2]);
                }
            }
        }
    }

    const int rm = m0 + wm + (lane >> 2);
    const int cn = n0 + wn + (lane & 3) * 2;
#pragma unroll
    for (int mt = 0; mt < 2; mt++)
#pragma unroll
        for (int nt = 0; nt < 8; nt++) {
            int gn = cn + nt * 8;
            float b0 = bias[gn], b1 = bias[gn + 1];
            int r0 = rm + mt * 16;
            float v00 = acc[mt][nt][0] + b0, v01 = acc[mt][nt][1] + b1;
            float v10 = acc[mt][nt][2] + b0, v11 = acc[mt][nt][3] + b1;
            if (EMODE == 0) {
                float2 a = { v00, v01 }, b = { v10, v11 };
                *(float2*)&C[(size_t)r0 * DM + gn]       = a;
                *(float2*)&C[(size_t)(r0 + 8) * DM + gn] = b;
            } else {
                int h = gn >> 6;
#pragma unroll
                for (int rr = 0; rr < 2; rr++) {
                    int r = r0 + rr * 8;
                    int s = r & 2047, bb = r >> 11;
                    int kk = (bb << 6) + (gn & 63);
                    size_t o = ((size_t)h * SQ + s) * 128 + kk;
                    uint32_t lo, hi;
                    hi = packsplit2(rr ? v10 : v00, rr ? v11 : v01, lo);
                    *(uint32_t*)&Oh[o] = hi;
                    *(uint32_t*)&Ol[o] = lo;
                }
            }
        }
}

// ---------------------------------------------------------------------------
// Prep: K fp32 -> transposed/negated SINGLE fp16 [h][kk=128][t]
// ---------------------------------------------------------------------------
__global__ __launch_bounds__(256) void kprep(const float* __restrict__ in,
                                             __half* __restrict__ oh)
{
    __shared__ float st[32][133];
    const int tid = threadIdx.x;
    const int h = blockIdx.x >> 6;
    const int t0 = (blockIdx.x & 63) * 32;
#pragma unroll
    for (int k = 0; k < 4; k++) {
        int i4 = tid + k * 256;
        int t = i4 >> 5, c4 = (i4 & 31) * 4;
        int b = c4 >> 6;
        float4 v = *(const float4*)&in[(size_t)(b * SQ + t0 + t) * DM + h * 64 + (c4 & 63)];
        if (b) { v.x = -v.x; v.y = -v.y; v.z = -v.z; v.w = -v.w; }
        st[t][c4] = v.x; st[t][c4 + 1] = v.y; st[t][c4 + 2] = v.z; st[t][c4 + 3] = v.w;
    }
    __syncthreads();
    const int kk = tid >> 1;
    const int th = (tid & 1) * 16;
    __half hv[16];
#pragma unroll
    for (int j = 0; j < 16; j++)
        hv[j] = __float2half_rn(st[th + j][kk]);
    size_t o = ((size_t)h * 128 + kk) * SQ + t0 + th;
    *(uint4*)&oh[o]     = *(uint4*)&hv[0];
    *(uint4*)&oh[o + 8] = *(uint4*)&hv[8];
}

// ---------------------------------------------------------------------------
// Prep: V1 column sums from fp16 V: o[h][c] = sum_t vh[h][t][64+c]
// ---------------------------------------------------------------------------
__global__ __launch_bounds__(256) void v1sum(const __half* __restrict__ vh,
                                             float* __restrict__ o)
{
    __shared__ float red[4][64];
    int h = blockIdx.x;
    int c = threadIdx.x & 63, q = threadIdx.x >> 6;
    float s = 0.f;
    for (int t = q * 512; t < (q + 1) * 512; t++)
        s += __half2float(vh[((size_t)h * SQ + t) * 128 + 64 + c]);
    red[q][c] = s;
    __syncthreads();
    if (threadIdx.x < 64)
        o[h * 64 + threadIdx.x] = red[0][threadIdx.x] + red[1][threadIdx.x]
                                + red[2][threadIdx.x] + red[3][threadIdx.x];
}

// ---------------------------------------------------------------------------
// fp16 fused attention: Q split hi/lo, K single, V single, 2-term mma.
// smem (fp16 elems):
//   QL 0      [64][136]
//   KH 8704   [128][72]
//   VH 17920  [64][136]  (Q-hi staging at prologue)
//   PH 26624  [64][72]
//   PL 31232  [64][72]
// ---------------------------------------------------------------------------
#define O_QL  0
#define O_KH  8704
#define O_VH  17920
#define O_PH  26624
#define O_PL  31232
#define ATTN_SMEM (35840 * 2)

__global__ void __launch_bounds__(256, 2) attn_tc(
    const __half* __restrict__ qh_g, const __half* __restrict__ ql_g,
    const __half* __restrict__ kth,  const __half* __restrict__ vh_g,
    const float* __restrict__ v1s,
    __half* __restrict__ aoh, __half* __restrict__ aol)
{
    extern __shared__ __half sm[];
    const uint32_t sb = s2u(sm);
    const int tid = threadIdx.x;
    const int wid = tid >> 5, lane = tid & 31;
    const int s0 = blockIdx.x * 64;
    const int h  = blockIdx.y;

    const int wm  = (wid & 3) * 16;
    const int wnt = (wid >> 2) * 32;
    const int wnc = (wid >> 2) * 64;

    const uint32_t aQl = sb + O_QL * 2 + ((wm + (lane & 15)) * 136 + (lane >> 4) * 8) * 2;
    const uint32_t bKh = sb + O_KH * 2 + ((lane & 15) * 72 + wnt + (lane >> 4) * 8) * 2;
    const uint32_t aPh = sb + O_PH * 2 + ((wm + (lane & 15)) * 72 + (lane >> 4) * 8) * 2;
    const uint32_t aPl = sb + O_PL * 2 + ((wm + (lane & 15)) * 72 + (lane >> 4) * 8) * 2;
    const uint32_t bVh = sb + O_VH * 2 + ((lane & 15) * 136 + wnc + (lane >> 4) * 8) * 2;

    // group 0: Q-hi -> VH staging, Q-lo -> QL (2048 chunks)
#pragma unroll
    for (int k = 0; k < 8; k++) {
        int c = tid + k * 256;
        int arr = c >> 10, rem = c & 1023;
        int r = rem >> 4, j = rem & 15;
        const __half* src = (arr ? ql_g : qh_g)
            + ((size_t)h * SQ + s0 + r) * 128 + j * 8;
        uint32_t dst = sb + (arr ? O_QL : O_VH) * 2 + (uint32_t)(r * 136 + j * 8) * 2;
        cpa16(dst, src);
    }
    cpcommit();
    // group 1: K(0) single (1024 chunks: 128 rows x 8)
#pragma unroll
    for (int k = 0; k < 4; k++) {
        int c = tid + k * 256;
        int kk = c >> 3, j = c & 7;
        const __half* src = kth + ((size_t)h * 128 + kk) * SQ + j * 8;
        uint32_t dst = sb + O_KH * 2 + (uint32_t)(kk * 72 + j * 8) * 2;
        cpa16(dst, src);
    }
    cpcommit();
    cpwait1();
    __syncthreads();

    uint32_t qhf[8][4];
    {
        uint32_t aQh = sb + O_VH * 2 + ((wm + (lane & 15)) * 136 + (lane >> 4) * 8) * 2;
#pragma unroll
        for (int ks = 0; ks < 8; ks++)
            ldsm4(qhf[ks], aQh + (uint32_t)(ks * 16) * 2);
    }
    __syncthreads();

    // group 2: V(0) single (1024 chunks: 64 rows x 16)
#pragma unroll
    for (int k = 0; k < 4; k++) {
        int c = tid + k * 256;
        int r = c >> 4, j = c & 15;
        const __half* src = vh_g + ((size_t)h * SQ + r) * 128 + j * 8;
        uint32_t dst = sb + O_VH * 2 + (uint32_t)(r * 136 + j * 8) * 2;
        cpa16(dst, src);
    }
    cpcommit();

    float acc[8][4];
#pragma unroll
    for (int f = 0; f < 8; f++)
#pragma unroll
        for (int j = 0; j < 4; j++) acc[f][j] = 0.f;

    for (int t0 = 0; t0 < SQ; t0 += 64) {
        cpwait1();       // K(i) landed
        __syncthreads();

        // ---- score: Qh(reg)*K + Ql*K ----
        float sc[4][4];
#pragma unroll
        for (int g = 0; g < 4; g++)
#pragma unroll
            for (int j = 0; j < 4; j++) sc[g][j] = 0.f;
#pragma unroll
        for (int ks = 0; ks < 8; ks++) {
            uint32_t ql4[4], kh[2][4];
            ldsm4(ql4, aQl + (uint32_t)(ks * 16) * 2);
#pragma unroll
            for (int p = 0; p < 2; p++)
                ldsm4t(kh[p], bKh + (uint32_t)(ks * 16 * 72 + p * 16) * 2);
#pragma unroll
            for (int p = 0; p < 2; p++) {
                mma16816(sc[2 * p],     qhf[ks], &kh[p][0]);
                mma16816(sc[2 * p + 1], qhf[ks], &kh[p][2]);
                mma16816(sc[2 * p],     ql4,     &kh[p][0]);
                mma16816(sc[2 * p + 1], ql4,     &kh[p][2]);
            }
        }

        // ---- sigmoid + split P ----
        {
            int r0 = wm + (lane >> 2);
            int cb = wnt + (lane & 3) * 2;
#pragma unroll
            for (int g = 0; g < 4; g++) {
                float p0 = 1.f / (1.f + __expf(-0.125f * sc[g][0]));
                float p1 = 1.f / (1.f + __expf(-0.125f * sc[g][1]));
                float p2 = 1.f / (1.f + __expf(-0.125f * sc[g][2]));
                float p3 = 1.f / (1.f + __expf(-0.125f * sc[g][3]));
                uint32_t lo, hi;
                int i0 = r0 * 72 + cb + 8 * g;
                int i1 = (r0 + 8) * 72 + cb + 8 * g;
                hi = packsplit2(p0, p1, lo);
                *(uint32_t*)&sm[O_PH + i0] = hi;  *(uint32_t*)&sm[O_PL + i0] = lo;
                hi = packsplit2(p2, p3, lo);
                *(uint32_t*)&sm[O_PH + i1] = hi;  *(uint32_t*)&sm[O_PL + i1] = lo;
            }
        }
        __syncthreads();

        // prefetch K(i+1)
        if (t0 + 64 < SQ) {
#pragma unroll
            for (int k = 0; k < 4; k++) {
                int c = tid + k * 256;
                int kk = c >> 3, j = c & 7;
                const __half* src = kth + ((size_t)h * 128 + kk) * SQ + (t0 + 64) + j * 8;
                uint32_t dst = sb + O_KH * 2 + (uint32_t)(kk * 72 + j * 8) * 2;
                cpa16(dst, src);
            }
        }
        cpcommit();

        cpwait1();       // V(i) landed
        __syncthreads();

        // ---- PV: Ph*V + Pl*V ----
#pragma unroll
        for (int ks = 0; ks < 4; ks++) {
            uint32_t ph4[4], pl4[4], vh4[4][4];
            ldsm4(ph4, aPh + (uint32_t)(ks * 16) * 2);
            ldsm4(pl4, aPl + (uint32_t)(ks * 16) * 2);
#pragma unroll
            for (int p = 0; p < 4; p++)
                ldsm4t(vh4[p], bVh + (uint32_t)(ks * 16 * 136 + p * 16) * 2);
#pragma unroll
            for (int p = 0; p < 4; p++) {
                mma16816(acc[2 * p],     ph4, &vh4[p][0]);
                mma16816(acc[2 * p + 1], ph4, &vh4[p][2]);
                mma16816(acc[2 * p],     pl4, &vh4[p][0]);
                mma16816(acc[2 * p + 1], pl4, &vh4[p][2]);
            }
        }
        __syncthreads();

        // prefetch V(i+1)
        if (t0 + 64 < SQ) {
#pragma unroll
            for (int k = 0; k < 4; k++) {
                int c = tid + k * 256;
                int r = c >> 4, j = c & 15;
                const __half* src = vh_g + ((size_t)h * SQ + (t0 + 64) + r) * 128 + j * 8;
                uint32_t dst = sb + O_VH * 2 + (uint32_t)(r * 136 + j * 8) * 2;
                cpa16(dst, src);
            }
        }
        cpcommit();
    }
    cpwait0();

    // epilogue: split-write for final GEMM (b=1 uses V1sum - acc)
    {
        int r0 = s0 + wm + (lane >> 2);
#pragma unroll
        for (int f = 0; f < 8; f++) {
            int c = wnc + 8 * f + (lane & 3) * 2;
            int b = c >> 6;
            size_t o = ((size_t)b * SQ + r0) * DM + h * 64 + (c & 63);
            float v00, v01, v10, v11;
            if (b) {
                float sA = v1s[h * 64 + (c & 63)];
                float sB = v1s[h * 64 + (c & 63) + 1];
                v00 = sA - acc[f][0]; v01 = sB - acc[f][1];
                v10 = sA - acc[f][2]; v11 = sB - acc[f][3];
            } else {
                v00 = acc[f][0]; v01 = acc[f][1];
                v10 = acc[f][2]; v11 = acc[f][3];
            }
            uint32_t lo, hi;
            hi = packsplit2(v00, v01, lo);
            *(uint32_t*)&aoh[o] = hi; *(uint32_t*)&aol[o] = lo;
            hi = packsplit2(v10, v11, lo);
            *(uint32_t*)&aoh[o + 8 * DM] = hi; *(uint32_t*)&aol[o + 8 * DM] = lo;
        }
    }
}

// ---------------------------------------------------------------------------
extern "C" void kernel_launch(void* const* d_in, const int* in_sizes, int n_in,
                              void* d_out, int out_size)
{
    const float* query = (const float*)d_in[0];
    const float* key   = (const float*)d_in[1];
    const float* value = (const float*)d_in[2];
    const float* Wq = (const float*)d_in[3];
    const float* bq = (const float*)d_in[4];
    const float* Wk = (const float*)d_in[5];
    const float* bk = (const float*)d_in[6];
    const float* Wv = (const float*)d_in[7];
    const float* bv = (const float*)d_in[8];
    const float* Wo = (const float*)d_in[9];
    const float* bo = (const float*)d_in[10];
    float* out = (float*)d_out;

    float *kp, *v1sp;
    cudaGetSymbolAddress((void**)&kp,   g_k);
    cudaGetSymbolAddress((void**)&v1sp, g_v1s);
    __half *qAh,*qAl,*kAh,*kAl,*vAh,*vAl, *wq,*wk,*wv,*wo;
    __half *qhp,*qlp,*vhp,*vdp,*kthp,*aohp,*aolp;
    cudaGetSymbolAddress((void**)&qAh, g_qAh); cudaGetSymbolAddress((void**)&qAl, g_qAl);
    cudaGetSymbolAddress((void**)&kAh, g_kAh); cudaGetSymbolAddress((void**)&kAl, g_kAl);
    cudaGetSymbolAddress((void**)&vAh, g_vAh); cudaGetSymbolAddress((void**)&vAl, g_vAl);
    cudaGetSymbolAddress((void**)&wq, g_wq);   cudaGetSymbolAddress((void**)&wk, g_wk);
    cudaGetSymbolAddress((void**)&wv, g_wv);   cudaGetSymbolAddress((void**)&wo, g_wo);
    cudaGetSymbolAddress((void**)&qhp, g_qh);  cudaGetSymbolAddress((void**)&qlp, g_ql);
    cudaGetSymbolAddress((void**)&vhp, g_vh);  cudaGetSymbolAddress((void**)&vdp, g_vdummy);
    cudaGetSymbolAddress((void**)&kthp, g_kth);
    cudaGetSymbolAddress((void**)&aohp, g_aoh); cudaGetSymbolAddress((void**)&aolp, g_aol);

    cudaFuncSetAttribute(attn_tc, cudaFuncAttributeMaxDynamicSharedMemorySize,
                         ATTN_SMEM);
    cudaFuncSetAttribute(gemm_hf<0>, cudaFuncAttributeMaxDynamicSharedMemorySize,
                         GEMM_SMEM);
    cudaFuncSetAttribute(gemm_hf<1>, cudaFuncAttributeMaxDynamicSharedMemorySize,
                         GEMM_SMEM);

    dim3 blk(256);
    dim3 gg(DM / 128, MR / 128);

    splitA<<<MR, blk>>>((const float4*)query, qAh, qAl);
    splitA<<<MR, blk>>>((const float4*)key,   kAh, kAl);
    splitA<<<MR, blk>>>((const float4*)value, vAh, vAl);
    roundW1<<<DM, blk>>>(Wq, wq);
    roundW1<<<DM, blk>>>(Wk, wk);
    roundW1<<<DM, blk>>>(Wv, wv);
    roundA<<<DM, blk>>>((const float4*)Wo, wo);

    gemm_hf<1><<<gg, blk, GEMM_SMEM>>>(qAh, qAl, wq, bq, nullptr, qhp, qlp);
    gemm_hf<0><<<gg, blk, GEMM_SMEM>>>(kAh, kAl, wk, bk, kp, nullptr, nullptr);
    gemm_hf<1><<<gg, blk, GEMM_SMEM>>>(vAh, vAl, wv, bv, nullptr, vhp, vdp);

    kprep<<<1024, blk>>>(kp, kthp);
    v1sum<<<NH, blk>>>(vhp, v1sp);

    attn_tc<<<dim3(SQ / 64, NH), blk, ATTN_SMEM>>>(qhp, qlp, kthp, vhp,
                                                   v1sp, aohp, aolp);

    gemm_hf<0><<<gg, blk, GEMM_SMEM>>>(aohp, aolp, wo, bo, out, nullptr, nullptr);
}

// round 11
// speedup vs baseline: 1.4013x; 1.4013x over previous
#include <cuda_runtime.h>
#include <cuda_fp16.h>
#include <cstdint>

#define SQ 2048
#define DM 1024
#define NH 16
#define MR 4096

static __device__ float g_k[MR*DM];
static __device__ float g_v1s[NH*64];
// single-fp16 rounded inputs + weights
static __device__ __half g_qA[MR*DM], g_kA[MR*DM], g_vA[MR*DM];
static __device__ __half g_wq[DM*DM], g_wk[DM*DM], g_wv[DM*DM], g_wo[DM*DM];
// attention operands (all single fp16)
static __device__ __half g_qh[NH*SQ*128];
static __device__ __half g_vh[NH*SQ*128];
static __device__ __half g_kth[NH*128*SQ];
// attention output, split hi/lo for the final 2-term GEMM
static __device__ __half g_aoh[MR*DM], g_aol[MR*DM];

// ---------------- PTX helpers ----------------
__device__ __forceinline__ uint32_t s2u(const void* p) {
    uint32_t a;
    asm("{ .reg .u64 t; cvta.to.shared.u64 t, %1; cvt.u32.u64 %0, t; }" : "=r"(a) : "l"(p));
    return a;
}
__device__ __forceinline__ void mma16816(float* d, const uint32_t* a, const uint32_t* b) {
    asm volatile(
        "mma.sync.aligned.m16n8k16.row.col.f32.f16.f16.f32 "
        "{%0,%1,%2,%3}, {%4,%5,%6,%7}, {%8,%9}, {%0,%1,%2,%3};"
        : "+f"(d[0]), "+f"(d[1]), "+f"(d[2]), "+f"(d[3])
        : "r"(a[0]), "r"(a[1]), "r"(a[2]), "r"(a[3]), "r"(b[0]), "r"(b[1]));
}
__device__ __forceinline__ void ldsm4(uint32_t* r, uint32_t addr) {
    asm volatile("ldmatrix.sync.aligned.m8n8.x4.shared.b16 {%0,%1,%2,%3}, [%4];"
        : "=r"(r[0]), "=r"(r[1]), "=r"(r[2]), "=r"(r[3]) : "r"(addr));
}
__device__ __forceinline__ void ldsm4t(uint32_t* r, uint32_t addr) {
    asm volatile("ldmatrix.sync.aligned.m8n8.x4.trans.shared.b16 {%0,%1,%2,%3}, [%4];"
        : "=r"(r[0]), "=r"(r[1]), "=r"(r[2]), "=r"(r[3]) : "r"(addr));
}
__device__ __forceinline__ void cpa16(uint32_t dst, const void* src) {
    asm volatile("cp.async.cg.shared.global [%0], [%1], 16;" :: "r"(dst), "l"(src));
}
__device__ __forceinline__ void cpcommit() {
    asm volatile("cp.async.commit_group;" ::: "memory");
}
__device__ __forceinline__ void cpwait1() {
    asm volatile("cp.async.wait_group 1;" ::: "memory");
}
__device__ __forceinline__ void cpwait0() {
    asm volatile("cp.async.wait_group 0;" ::: "memory");
}
__device__ __forceinline__ uint32_t pack2(__half a, __half b) {
    __half2 t = __halves2half2(a, b);
    return *reinterpret_cast<uint32_t*>(&t);
}
__device__ __forceinline__ uint2 round4(float4 v) {
    uint2 r;
    r.x = pack2(__float2half_rn(v.x), __float2half_rn(v.y));
    r.y = pack2(__float2half_rn(v.z), __float2half_rn(v.w));
    return r;
}
__device__ __forceinline__ uint32_t packsplit2(float a, float b, uint32_t& lo) {
    __half ah = __float2half_rn(a), bh = __float2half_rn(b);
    __half al = __float2half_rn(a - __half2float(ah));
    __half bl = __float2half_rn(b - __half2float(bh));
    lo = pack2(al, bl);
    return pack2(ah, bh);
}

// ---------------------------------------------------------------------------
// Prep: round fp32 [R][1024] -> single fp16 (inputs, Wo)
// ---------------------------------------------------------------------------
__global__ __launch_bounds__(256) void roundA(const float4* __restrict__ A,
                                              __half* __restrict__ o)
{
    size_t i = (size_t)blockIdx.x * 256 + threadIdx.x;
    *(uint2*)&o[i * 4] = round4(A[i]);
}

// Prep: stacked W [16][1024][64] -> single fp16 W'[k][c]
__global__ __launch_bounds__(256) void roundW1(const float* __restrict__ W,
                                               __half* __restrict__ o)
{
    size_t i = (size_t)blockIdx.x * 256 + threadIdx.x;
    int k = (int)(i >> 8);
    int c4 = (int)(i & 255) * 4;
    float4 v = *(const float4*)&W[((size_t)(c4 >> 6) * DM + k) * 64 + (c4 & 63)];
    *(uint2*)&o[(size_t)k * DM + c4] = round4(v);
}

// ---------------------------------------------------------------------------
// fp16 GEMM, cp.async 2-stage pipeline.
// SPLIT 1: A = Ah+Al (2-term). SPLIT 0: A = Ah only.
// EMODE 0: fp32 C. EMODE 1: split fp16 out (attn layout). EMODE 2: single
// fp16 out (attn layout).
// ---------------------------------------------------------------------------
#define GA_ST 40
#define GB_ST 136
#define SA_SZ (128*GA_ST)
#define SB_SZ (32*GB_ST)
#define OFF_AH(s) ((s)*SA_SZ)
#define OFF_AL(s) (2*SA_SZ + (s)*SA_SZ)
#define OFF_B(s)  (4*SA_SZ + (s)*SB_SZ)
#define GEMM_SMEM ((4*SA_SZ + 2*SB_SZ) * 2)   // 58368 B

template<int EMODE, int SPLIT>
__global__ void __launch_bounds__(256, 2) gemm_hf(
    const __half* __restrict__ Ah_g, const __half* __restrict__ Al_g,
    const __half* __restrict__ B_g,
    const float* __restrict__ bias,
    float* __restrict__ C,
    __half* __restrict__ Oh, __half* __restrict__ Ol)
{
    extern __shared__ __half gsm[];
    const uint32_t sb = s2u(gsm);
    const int tid = threadIdx.x;
    const int wid = tid >> 5, lane = tid & 31;
    const int m0 = blockIdx.y * 128, n0 = blockIdx.x * 128;
    const int wm = (wid & 3) * 32;
    const int wn = (wid >> 2) * 64;

    float acc[2][8][4];
#pragma unroll
    for (int i = 0; i < 2; i++)
#pragma unroll
        for (int j = 0; j < 8; j++)
#pragma unroll
            for (int k = 0; k < 4; k++) acc[i][j][k] = 0.f;

    const int aOff = (wm + (lane & 15)) * GA_ST + (lane >> 4) * 8;
    const int bOff = (lane & 15) * GB_ST + wn + (lane >> 4) * 8;

    auto loadStage = [&](int s, int k0) {
#pragma unroll
        for (int t = 0; t < 2; t++) {               // A hi: 512 chunks
            int c = tid + t * 256;
            int m = c >> 2, j = c & 3;
            const __half* src = Ah_g + (size_t)(m0 + m) * DM + k0 + j * 8;
            uint32_t dst = sb + (uint32_t)(OFF_AH(s) + m * GA_ST + j * 8) * 2;
            cpa16(dst, src);
        }
        if (SPLIT) {
#pragma unroll
            for (int t = 0; t < 2; t++) {           // A lo: 512 chunks
                int c = tid + t * 256;
                int m = c >> 2, j = c & 3;
                const __half* src = Al_g + (size_t)(m0 + m) * DM + k0 + j * 8;
                uint32_t dst = sb + (uint32_t)(OFF_AL(s) + m * GA_ST + j * 8) * 2;
                cpa16(dst, src);
            }
        }
#pragma unroll
        for (int t = 0; t < 2; t++) {               // B: 512 chunks
            int c = tid + t * 256;
            int k = c >> 4, j = c & 15;
            const __half* src = B_g + (size_t)(k0 + k) * DM + n0 + j * 8;
            uint32_t dst = sb + (uint32_t)(OFF_B(s) + k * GB_ST + j * 8) * 2;
            cpa16(dst, src);
        }
    };

    loadStage(0, 0);
    cpcommit();

    for (int i = 0; i < 32; i++) {
        cpwait0();
        __syncthreads();
        if (i + 1 < 32) {
            loadStage((i + 1) & 1, (i + 1) * 32);
            cpcommit();
        }
        const int s = i & 1;
        const uint32_t ahB = sb + (uint32_t)(OFF_AH(s) + aOff) * 2;
        const uint32_t alB = sb + (uint32_t)(OFF_AL(s) + aOff) * 2;
        const uint32_t bB  = sb + (uint32_t)(OFF_B(s)  + bOff) * 2;
#pragma unroll
        for (int k16 = 0; k16 < 32; k16 += 16) {
            uint32_t ah[2][4], al[2][4];
            ldsm4(ah[0], ahB + (uint32_t)k16 * 2);
            ldsm4(ah[1], ahB + (uint32_t)(16 * GA_ST + k16) * 2);
            if (SPLIT) {
                ldsm4(al[0], alB + (uint32_t)k16 * 2);
                ldsm4(al[1], alB + (uint32_t)(16 * GA_ST + k16) * 2);
            }
#pragma unroll
            for (int p = 0; p < 4; p++) {
                uint32_t b4[4];
                ldsm4t(b4, bB + (uint32_t)(k16 * GB_ST + p * 16) * 2);
#pragma unroll
                for (int mt = 0; mt < 2; mt++) {
                    mma16816(acc[mt][2 * p],     ah[mt], &b4[0]);
                    mma16816(acc[mt][2 * p + 1], ah[mt], &b4[2]);
                    if (SPLIT) {
                        mma16816(acc[mt][2 * p],     al[mt], &b4[0]);
                        mma16816(acc[mt][2 * p + 1], al[mt], &b4[2]);
                    }
                }
            }
        }
    }

    const int rm = m0 + wm + (lane >> 2);
    const int cn = n0 + wn + (lane & 3) * 2;
#pragma unroll
    for (int mt = 0; mt < 2; mt++)
#pragma unroll
        for (int nt = 0; nt < 8; nt++) {
            int gn = cn + nt * 8;
            float b0 = bias[gn], b1 = bias[gn + 1];
            int r0 = rm + mt * 16;
            float v00 = acc[mt][nt][0] + b0, v01 = acc[mt][nt][1] + b1;
            float v10 = acc[mt][nt][2] + b0, v11 = acc[mt][nt][3] + b1;
            if (EMODE == 0) {
                float2 a = { v00, v01 }, b = { v10, v11 };
                *(float2*)&C[(size_t)r0 * DM + gn]       = a;
                *(float2*)&C[(size_t)(r0 + 8) * DM + gn] = b;
            } else {
                int h = gn >> 6;
#pragma unroll
                for (int rr = 0; rr < 2; rr++) {
                    int r = r0 + rr * 8;
                    int s = r & 2047, bb = r >> 11;
                    int kk = (bb << 6) + (gn & 63);
                    size_t o = ((size_t)h * SQ + s) * 128 + kk;
                    float va = rr ? v10 : v00, vb = rr ? v11 : v01;
                    if (EMODE == 1) {
                        uint32_t lo, hi;
                        hi = packsplit2(va, vb, lo);
                        *(uint32_t*)&Oh[o] = hi;
                        *(uint32_t*)&Ol[o] = lo;
                    } else {
                        *(uint32_t*)&Oh[o] =
                            pack2(__float2half_rn(va), __float2half_rn(vb));
                    }
                }
            }
        }
}

// ---------------------------------------------------------------------------
// Prep: K fp32 -> transposed/negated single fp16 [h][kk=128][t]
// ---------------------------------------------------------------------------
__global__ __launch_bounds__(256) void kprep(const float* __restrict__ in,
                                             __half* __restrict__ oh)
{
    __shared__ float st[32][133];
    const int tid = threadIdx.x;
    const int h = blockIdx.x >> 6;
    const int t0 = (blockIdx.x & 63) * 32;
#pragma unroll
    for (int k = 0; k < 4; k++) {
        int i4 = tid + k * 256;
        int t = i4 >> 5, c4 = (i4 & 31) * 4;
        int b = c4 >> 6;
        float4 v = *(const float4*)&in[(size_t)(b * SQ + t0 + t) * DM + h * 64 + (c4 & 63)];
        if (b) { v.x = -v.x; v.y = -v.y; v.z = -v.z; v.w = -v.w; }
        st[t][c4] = v.x; st[t][c4 + 1] = v.y; st[t][c4 + 2] = v.z; st[t][c4 + 3] = v.w;
    }
    __syncthreads();
    const int kk = tid >> 1;
    const int th = (tid & 1) * 16;
    __half hv[16];
#pragma unroll
    for (int j = 0; j < 16; j++)
        hv[j] = __float2half_rn(st[th + j][kk]);
    size_t o = ((size_t)h * 128 + kk) * SQ + t0 + th;
    *(uint4*)&oh[o]     = *(uint4*)&hv[0];
    *(uint4*)&oh[o + 8] = *(uint4*)&hv[8];
}

// ---------------------------------------------------------------------------
// Prep: V1 column sums
// ---------------------------------------------------------------------------
__global__ __launch_bounds__(256) void v1sum(const __half* __restrict__ vh,
                                             float* __restrict__ o)
{
    __shared__ float red[4][64];
    int h = blockIdx.x;
    int c = threadIdx.x & 63, q = threadIdx.x >> 6;
    float s = 0.f;
    for (int t = q * 512; t < (q + 1) * 512; t++)
        s += __half2float(vh[((size_t)h * SQ + t) * 128 + 64 + c]);
    red[q][c] = s;
    __syncthreads();
    if (threadIdx.x < 64)
        o[h * 64 + threadIdx.x] = red[0][threadIdx.x] + red[1][threadIdx.x]
                                + red[2][threadIdx.x] + red[3][threadIdx.x];
}

// ---------------------------------------------------------------------------
// Single-fp16 fused attention: Q regs, K single, P single, V single.
// smem (fp16 elems): KH 0 [128][72], VH 9216 [64][136] (Q staging), PH 17920 [64][72]
// ---------------------------------------------------------------------------
#define A_KH  0
#define A_VH  9216
#define A_PH  17920
#define ATTN_SMEM (22528 * 2)

__global__ void __launch_bounds__(256, 2) attn_tc(
    const __half* __restrict__ qh_g, const __half* __restrict__ kth,
    const __half* __restrict__ vh_g,
    const float* __restrict__ v1s,
    __half* __restrict__ aoh, __half* __restrict__ aol)
{
    extern __shared__ __half sm[];
    const uint32_t sb = s2u(sm);
    const int tid = threadIdx.x;
    const int wid = tid >> 5, lane = tid & 31;
    const int s0 = blockIdx.x * 64;
    const int h  = blockIdx.y;

    const int wm  = (wid & 3) * 16;
    const int wnt = (wid >> 2) * 32;
    const int wnc = (wid >> 2) * 64;

    const uint32_t bKh = sb + A_KH * 2 + ((lane & 15) * 72 + wnt + (lane >> 4) * 8) * 2;
    const uint32_t aPh = sb + A_PH * 2 + ((wm + (lane & 15)) * 72 + (lane >> 4) * 8) * 2;
    const uint32_t bVh = sb + A_VH * 2 + ((lane & 15) * 136 + wnc + (lane >> 4) * 8) * 2;

    // group 0: Q -> VH staging (64 rows x 16 chunks)
#pragma unroll
    for (int k = 0; k < 4; k++) {
        int c = tid + k * 256;
        int r = c >> 4, j = c & 15;
        const __half* src = qh_g + ((size_t)h * SQ + s0 + r) * 128 + j * 8;
        cpa16(sb + A_VH * 2 + (uint32_t)(r * 136 + j * 8) * 2, src);
    }
    cpcommit();
    // group 1: K(0) (128 rows x 8 chunks)
#pragma unroll
    for (int k = 0; k < 4; k++) {
        int c = tid + k * 256;
        int kk = c >> 3, j = c & 7;
        const __half* src = kth + ((size_t)h * 128 + kk) * SQ + j * 8;
        cpa16(sb + A_KH * 2 + (uint32_t)(kk * 72 + j * 8) * 2, src);
    }
    cpcommit();
    cpwait1();
    __syncthreads();

    uint32_t qhf[8][4];
    {
        uint32_t aQh = sb + A_VH * 2 + ((wm + (lane & 15)) * 136 + (lane >> 4) * 8) * 2;
#pragma unroll
        for (int ks = 0; ks < 8; ks++)
            ldsm4(qhf[ks], aQh + (uint32_t)(ks * 16) * 2);
    }
    __syncthreads();

    // group 2: V(0) (64 rows x 16 chunks)
#pragma unroll
    for (int k = 0; k < 4; k++) {
        int c = tid + k * 256;
        int r = c >> 4, j = c & 15;
        const __half* src = vh_g + ((size_t)h * SQ + r) * 128 + j * 8;
        cpa16(sb + A_VH * 2 + (uint32_t)(r * 136 + j * 8) * 2, src);
    }
    cpcommit();

    float acc[8][4];
#pragma unroll
    for (int f = 0; f < 8; f++)
#pragma unroll
        for (int j = 0; j < 4; j++) acc[f][j] = 0.f;

    for (int t0 = 0; t0 < SQ; t0 += 64) {
        cpwait1();       // K(i) landed
        __syncthreads();

        // ---- score: Qh(reg) * K ----
        float sc[4][4];
#pragma unroll
        for (int g = 0; g < 4; g++)
#pragma unroll
            for (int j = 0; j < 4; j++) sc[g][j] = 0.f;
#pragma unroll
        for (int ks = 0; ks < 8; ks++) {
            uint32_t kh[2][4];
#pragma unroll
            for (int p = 0; p < 2; p++)
                ldsm4t(kh[p], bKh + (uint32_t)(ks * 16 * 72 + p * 16) * 2);
#pragma unroll
            for (int p = 0; p < 2; p++) {
                mma16816(sc[2 * p],     qhf[ks], &kh[p][0]);
                mma16816(sc[2 * p + 1], qhf[ks], &kh[p][2]);
            }
        }

        // ---- sigmoid + single-fp16 P ----
        {
            int r0 = wm + (lane >> 2);
            int cb = wnt + (lane & 3) * 2;
#pragma unroll
            for (int g = 0; g < 4; g++) {
                float p0 = 1.f / (1.f + __expf(-0.125f * sc[g][0]));
                float p1 = 1.f / (1.f + __expf(-0.125f * sc[g][1]));
                float p2 = 1.f / (1.f + __expf(-0.125f * sc[g][2]));
                float p3 = 1.f / (1.f + __expf(-0.125f * sc[g][3]));
                int i0 = r0 * 72 + cb + 8 * g;
                int i1 = (r0 + 8) * 72 + cb + 8 * g;
                *(uint32_t*)&sm[A_PH + i0] =
                    pack2(__float2half_rn(p0), __float2half_rn(p1));
                *(uint32_t*)&sm[A_PH + i1] =
                    pack2(__float2half_rn(p2), __float2half_rn(p3));
            }
        }
        __syncthreads();

        // prefetch K(i+1)
        if (t0 + 64 < SQ) {
#pragma unroll
            for (int k = 0; k < 4; k++) {
                int c = tid + k * 256;
                int kk = c >> 3, j = c & 7;
                const __half* src = kth + ((size_t)h * 128 + kk) * SQ + (t0 + 64) + j * 8;
                cpa16(sb + A_KH * 2 + (uint32_t)(kk * 72 + j * 8) * 2, src);
            }
        }
        cpcommit();

        cpwait1();       // V(i) landed
        __syncthreads();

        // ---- PV: P * V ----
#pragma unroll
        for (int ks = 0; ks < 4; ks++) {
            uint32_t ph4[4], vh4[4][4];
            ldsm4(ph4, aPh + (uint32_t)(ks * 16) * 2);
#pragma unroll
            for (int p = 0; p < 4; p++)
                ldsm4t(vh4[p], bVh + (uint32_t)(ks * 16 * 136 + p * 16) * 2);
#pragma unroll
            for (int p = 0; p < 4; p++) {
                mma16816(acc[2 * p],     ph4, &vh4[p][0]);
                mma16816(acc[2 * p + 1], ph4, &vh4[p][2]);
            }
        }
        __syncthreads();

        // prefetch V(i+1)
        if (t0 + 64 < SQ) {
#pragma unroll
            for (int k = 0; k < 4; k++) {
                int c = tid + k * 256;
                int r = c >> 4, j = c & 15;
                const __half* src = vh_g + ((size_t)h * SQ + (t0 + 64) + r) * 128 + j * 8;
                cpa16(sb + A_VH * 2 + (uint32_t)(r * 136 + j * 8) * 2, src);
            }
        }
        cpcommit();
    }
    cpwait0();

    // epilogue: split hi/lo for the final 2-term GEMM (b=1: V1sum - acc)
    {
        int r0 = s0 + wm + (lane >> 2);
#pragma unroll
        for (int f = 0; f < 8; f++) {
            int c = wnc + 8 * f + (lane & 3) * 2;
            int b = c >> 6;
            size_t o = ((size_t)b * SQ + r0) * DM + h * 64 + (c & 63);
            float v00, v01, v10, v11;
            if (b) {
                float sA = v1s[h * 64 + (c & 63)];
                float sB = v1s[h * 64 + (c & 63) + 1];
                v00 = sA - acc[f][0]; v01 = sB - acc[f][1];
                v10 = sA - acc[f][2]; v11 = sB - acc[f][3];
            } else {
                v00 = acc[f][0]; v01 = acc[f][1];
                v10 = acc[f][2]; v11 = acc[f][3];
            }
            uint32_t lo, hi;
            hi = packsplit2(v00, v01, lo);
            *(uint32_t*)&aoh[o] = hi; *(uint32_t*)&aol[o] = lo;
            hi = packsplit2(v10, v11, lo);
            *(uint32_t*)&aoh[o + 8 * DM] = hi; *(uint32_t*)&aol[o + 8 * DM] = lo;
        }
    }
}

// ---------------------------------------------------------------------------
extern "C" void kernel_launch(void* const* d_in, const int* in_sizes, int n_in,
                              void* d_out, int out_size)
{
    const float* query = (const float*)d_in[0];
    const float* key   = (const float*)d_in[1];
    const float* value = (const float*)d_in[2];
    const float* Wq = (const float*)d_in[3];
    const float* bq = (const float*)d_in[4];
    const float* Wk = (const float*)d_in[5];
    const float* bk = (const float*)d_in[6];
    const float* Wv = (const float*)d_in[7];
    const float* bv = (const float*)d_in[8];
    const float* Wo = (const float*)d_in[9];
    const float* bo = (const float*)d_in[10];
    float* out = (float*)d_out;

    float *kp, *v1sp;
    cudaGetSymbolAddress((void**)&kp,   g_k);
    cudaGetSymbolAddress((void**)&v1sp, g_v1s);
    __half *qA,*kA,*vA, *wq,*wk,*wv,*wo;
    __half *qhp,*vhp,*kthp,*aohp,*aolp;
    cudaGetSymbolAddress((void**)&qA, g_qA);
    cudaGetSymbolAddress((void**)&kA, g_kA);
    cudaGetSymbolAddress((void**)&vA, g_vA);
    cudaGetSymbolAddress((void**)&wq, g_wq);   cudaGetSymbolAddress((void**)&wk, g_wk);
    cudaGetSymbolAddress((void**)&wv, g_wv);   cudaGetSymbolAddress((void**)&wo, g_wo);
    cudaGetSymbolAddress((void**)&qhp, g_qh);  cudaGetSymbolAddress((void**)&vhp, g_vh);
    cudaGetSymbolAddress((void**)&kthp, g_kth);
    cudaGetSymbolAddress((void**)&aohp, g_aoh); cudaGetSymbolAddress((void**)&aolp, g_aol);

    cudaFuncSetAttribute(attn_tc, cudaFuncAttributeMaxDynamicSharedMemorySize,
                         ATTN_SMEM);
    cudaFuncSetAttribute((gemm_hf<0,0>), cudaFuncAttributeMaxDynamicSharedMemorySize,
                         GEMM_SMEM);
    cudaFuncSetAttribute((gemm_hf<2,0>), cudaFuncAttributeMaxDynamicSharedMemorySize,
                         GEMM_SMEM);
    cudaFuncSetAttribute((gemm_hf<0,1>), cudaFuncAttributeMaxDynamicSharedMemorySize,
                         GEMM_SMEM);

    dim3 blk(256);
    dim3 gg(DM / 128, MR / 128);

    roundA<<<MR, blk>>>((const float4*)query, qA);
    roundA<<<MR, blk>>>((const float4*)key,   kA);
    roundA<<<MR, blk>>>((const float4*)value, vA);
    roundW1<<<DM, blk>>>(Wq, wq);
    roundW1<<<DM, blk>>>(Wk, wk);
    roundW1<<<DM, blk>>>(Wv, wv);
    roundA<<<DM, blk>>>((const float4*)Wo, wo);

    // 1-term projections (outputs are fp16 anyway)
    gemm_hf<2,0><<<gg, blk, GEMM_SMEM>>>(qA, nullptr, wq, bq, nullptr, qhp, nullptr);
    gemm_hf<0,0><<<gg, blk, GEMM_SMEM>>>(kA, nullptr, wk, bk, kp, nullptr, nullptr);
    gemm_hf<2,0><<<gg, blk, GEMM_SMEM>>>(vA, nullptr, wv, bv, nullptr, vhp, nullptr);

    kprep<<<1024, blk>>>(kp, kthp);
    v1sum<<<NH, blk>>>(vhp, v1sp);

    attn_tc<<<dim3(SQ / 64, NH), blk, ATTN_SMEM>>>(qhp, kthp, vhp,
                                                   v1sp, aohp, aolp);

    // output projection stays 2-term (error lands unattenuated on the result)
    gemm_hf<0,1><<<gg, blk, GEMM_SMEM>>>(aohp, aolp, wo, bo, out, nullptr, nullptr);
}